// round 2
// baseline (speedup 1.0000x reference)
#include <cuda_runtime.h>
#include <stdint.h>

#define LATENT 512
#define MCODES 1024
#define MAXN   65536

#define BM 128
#define BN 128
#define BKK 16
#define TM 8
#define TN 8
#define NTHREADS 256

// scratch (allocation-free rule: __device__ globals)
__device__ float g_a2[MAXN];
__device__ float g_b2[MCODES];

// one warp per row: sum of squares of 512 floats
__global__ void sumsq_kernel(const float* __restrict__ X, float* __restrict__ out, int nrows) {
    int warp = (blockIdx.x * blockDim.x + threadIdx.x) >> 5;
    int lane = threadIdx.x & 31;
    if (warp >= nrows) return;
    const float4* row = (const float4*)(X + (size_t)warp * LATENT);
    float s = 0.f;
#pragma unroll
    for (int i = 0; i < 4; i++) {
        float4 v = row[lane + i * 32];
        s += v.x * v.x + v.y * v.y + v.z * v.z + v.w * v.w;
    }
#pragma unroll
    for (int o = 16; o > 0; o >>= 1) s += __shfl_xor_sync(0xffffffffu, s, o);
    if (lane == 0) out[warp] = s;
}

// Fused: dist = a2 - 2*x@C^T + b2 ; write dist ; argmin per row ; gather codebook row.
__global__ __launch_bounds__(NTHREADS, 2)
void vq_kernel(const float* __restrict__ X, const float* __restrict__ C,
               float* __restrict__ quant, float* __restrict__ dist, int n)
{
    __shared__ float As[BKK][BM];
    __shared__ float Bs[BKK][BN];
    __shared__ float s_minv[BM][17];
    __shared__ int   s_mini[BM][17];

    const int tid = threadIdx.x;
    const int tr = tid / 16;          // 0..15 -> rows tr*8..tr*8+7
    const int tc = tid % 16;          // 0..15 -> cols tc*8..tc*8+7 (within tile)
    const int rowBase = blockIdx.x * BM;

    // A/B tile load mapping: tile is 128 rows x 16 k = 512 float4.
    // thread t loads float4 #t and #(t+256): row = idx>>2, kk = (idx&3)*4
    const int lRow0 = tid >> 2;
    const int lKK   = (tid & 3) * 4;

    float bestv[TM];
    int   besti[TM];
#pragma unroll
    for (int i = 0; i < TM; i++) { bestv[i] = 3.4e38f; besti[i] = 0; }

    for (int ct = 0; ct < MCODES / BN; ct++) {
        const int colBase = ct * BN;
        float acc[TM][TN];
#pragma unroll
        for (int i = 0; i < TM; i++)
#pragma unroll
            for (int j = 0; j < TN; j++) acc[i][j] = 0.f;

        for (int k0 = 0; k0 < LATENT; k0 += BKK) {
            // load A tile (transposed into As[k][row])
#pragma unroll
            for (int h = 0; h < 2; h++) {
                int row = lRow0 + h * 64;
                float4 av = *(const float4*)(X + (size_t)(rowBase + row) * LATENT + k0 + lKK);
                As[lKK + 0][row] = av.x;
                As[lKK + 1][row] = av.y;
                As[lKK + 2][row] = av.z;
                As[lKK + 3][row] = av.w;
                float4 bv = *(const float4*)(C + (size_t)(colBase + row) * LATENT + k0 + lKK);
                Bs[lKK + 0][row] = bv.x;
                Bs[lKK + 1][row] = bv.y;
                Bs[lKK + 2][row] = bv.z;
                Bs[lKK + 3][row] = bv.w;
            }
            __syncthreads();

#pragma unroll
            for (int k = 0; k < BKK; k++) {
                float4 m0 = *(const float4*)&As[k][tr * TM];
                float4 m1 = *(const float4*)&As[k][tr * TM + 4];
                float4 n0 = *(const float4*)&Bs[k][tc * TN];
                float4 n1 = *(const float4*)&Bs[k][tc * TN + 4];
                float rm[TM] = {m0.x, m0.y, m0.z, m0.w, m1.x, m1.y, m1.z, m1.w};
                float rn[TN] = {n0.x, n0.y, n0.z, n0.w, n1.x, n1.y, n1.z, n1.w};
#pragma unroll
                for (int i = 0; i < TM; i++)
#pragma unroll
                    for (int j = 0; j < TN; j++)
                        acc[i][j] += rm[i] * rn[j];
            }
            __syncthreads();
        }

        // epilogue: distance + dist write + running argmin
#pragma unroll
        for (int i = 0; i < TM; i++) {
            const int r = rowBase + tr * TM + i;
            const float a2 = g_a2[r];
            float dv[TN];
#pragma unroll
            for (int j = 0; j < TN; j++) {
                const int c = colBase + tc * TN + j;
                float d = a2 - 2.f * acc[i][j] + g_b2[c];
                dv[j] = d;
                if (d < bestv[i]) { bestv[i] = d; besti[i] = c; }
            }
            float* dp = dist + (size_t)r * MCODES + colBase + tc * TN;
            *(float4*)(dp + 0) = make_float4(dv[0], dv[1], dv[2], dv[3]);
            *(float4*)(dp + 4) = make_float4(dv[4], dv[5], dv[6], dv[7]);
        }
    }

    // cross-thread argmin reduction (16 partials per row)
#pragma unroll
    for (int i = 0; i < TM; i++) {
        s_minv[tr * TM + i][tc] = bestv[i];
        s_mini[tr * TM + i][tc] = besti[i];
    }
    __syncthreads();
    if (tid < BM) {
        float bv = s_minv[tid][0];
        int   bi = s_mini[tid][0];
#pragma unroll
        for (int t = 1; t < 16; t++) {
            float v = s_minv[tid][t];
            int   ix = s_mini[tid][t];
            if (v < bv || (v == bv && ix < bi)) { bv = v; bi = ix; }
        }
        s_mini[tid][16] = bi;
    }
    __syncthreads();

    // gather quantized rows: 128 rows x 128 float4
    for (int idx = tid; idx < BM * (LATENT / 4); idx += NTHREADS) {
        int r = idx >> 7;               // /128
        int q = idx & 127;
        int code = s_mini[r][16];
        ((float4*)(quant + (size_t)(rowBase + r) * LATENT))[q] =
            ((const float4*)(C + (size_t)code * LATENT))[q];
    }
}

extern "C" void kernel_launch(void* const* d_in, const int* in_sizes, int n_in,
                              void* d_out, int out_size) {
    const float* X = (const float*)d_in[0];
    const float* C = (const float*)d_in[1];
    const int n = in_sizes[0] / LATENT;   // 65536
    const int m = in_sizes[1] / LATENT;   // 1024

    float* quant = (float*)d_out;                       // (n, 512)
    float* dist  = (float*)d_out + (size_t)n * LATENT;  // (n, 1024)

    float* a2p = nullptr; float* b2p = nullptr;
    cudaGetSymbolAddress((void**)&a2p, g_a2);
    cudaGetSymbolAddress((void**)&b2p, g_b2);

    sumsq_kernel<<<(n + 7) / 8, 256>>>(X, a2p, n);
    sumsq_kernel<<<(m + 7) / 8, 256>>>(C, b2p, m);
    vq_kernel<<<n / BM, NTHREADS>>>(X, C, quant, dist, n);
}

// round 8
// speedup vs baseline: 4.3565x; 4.3565x over previous
#include <cuda_runtime.h>
#include <cuda_bf16.h>
#include <stdint.h>

#define LATENT 512
#define MCODES 1024

// ---------------- device scratch (no allocs allowed) ----------------
__device__ __nv_bfloat16 g_cb16[MCODES * LATENT];  // bf16 codebook (1MB, L2-resident)
__device__ float g_b2[MCODES];                     // codebook row sumsq (fp32)

// ---------------- smem layout (dynamic) ----------------
#define SM_A2    0                      // 128 floats
#define SM_B2    512                    // 1024 floats
#define SM_RV    4608                   // 128*2 floats (argmin reduce vals)
#define SM_MINV  5632                   // 128 floats (per-row bf16 min)
#define SM_CNT   6144                   // 8 ints (per-warp candidate count)
#define SM_CLIST 6208                   // 8*16 ints (per-warp candidate list)
#define SM_A     8192                   // 128x512 bf16 SW128-swizzled (128KB)
#define SM_B0    (SM_A + 131072)        // 128x128 bf16 chunk (32KB)
#define SM_B1    (SM_B0 + 32768)
#define SM_TOTAL (SM_B1 + 32768)        // 204800 bytes

__device__ __forceinline__ uint32_t su32(const void* p) {
    uint32_t a;
    asm("{ .reg .u64 t; cvta.to.shared.u64 t, %1; cvt.u32.u64 %0, t; }" : "=r"(a) : "l"(p));
    return a;
}

// SW128 blocked-atom offset: 8-row x 64-bf16 atoms (1KB), row-groups stride 1KB,
// k-groups stride 16KB. Works for both the A tile (128x512) and B chunks (128x128).
__device__ __forceinline__ uint32_t toff(int row, int k) {
    return (uint32_t)((row >> 3) * 1024 + (k >> 6) * 16384 + (row & 7) * 128 + (k & 63) * 2);
}
__device__ __forceinline__ uint32_t swz(uint32_t o) { return o ^ ((o >> 3) & 0x70); }

__device__ __forceinline__ void cp16(uint32_t dst, const void* src) {
    asm volatile("cp.async.cg.shared.global [%0], [%1], 16;" :: "r"(dst), "l"(src) : "memory");
}

__device__ __forceinline__ void ldsm4(uint32_t addr, uint32_t& r0, uint32_t& r1,
                                      uint32_t& r2, uint32_t& r3) {
    asm volatile("ldmatrix.sync.aligned.m8n8.x4.shared.b16 {%0,%1,%2,%3}, [%4];"
                 : "=r"(r0), "=r"(r1), "=r"(r2), "=r"(r3) : "r"(addr));
}

__device__ __forceinline__ void mma16816(float* d, uint32_t a0, uint32_t a1, uint32_t a2,
                                         uint32_t a3, uint32_t b0, uint32_t b1) {
    asm volatile(
        "mma.sync.aligned.m16n8k16.row.col.f32.bf16.bf16.f32 "
        "{%0,%1,%2,%3}, {%4,%5,%6,%7}, {%8,%9}, {%0,%1,%2,%3};"
        : "+f"(d[0]), "+f"(d[1]), "+f"(d[2]), "+f"(d[3])
        : "r"(a0), "r"(a1), "r"(a2), "r"(a3), "r"(b0), "r"(b1));
}

// ---------------- prep: bf16 codebook + b2 ----------------
__global__ void prep_kernel(const float* __restrict__ C) {
    int warp = (blockIdx.x * blockDim.x + threadIdx.x) >> 5;
    int lane = threadIdx.x & 31;
    if (warp >= MCODES) return;
    const float4* row = (const float4*)(C + (size_t)warp * LATENT);
    uint2* out = (uint2*)(g_cb16 + (size_t)warp * LATENT);
    float s = 0.f;
#pragma unroll
    for (int i = 0; i < 4; i++) {
        float4 v = row[lane + i * 32];
        s += v.x * v.x + v.y * v.y + v.z * v.z + v.w * v.w;
        __nv_bfloat162 p0 = __float22bfloat162_rn(make_float2(v.x, v.y));
        __nv_bfloat162 p1 = __float22bfloat162_rn(make_float2(v.z, v.w));
        uint2 pk;
        pk.x = *(uint32_t*)&p0;
        pk.y = *(uint32_t*)&p1;
        out[lane + i * 32] = pk;
    }
#pragma unroll
    for (int o = 16; o > 0; o >>= 1) s += __shfl_xor_sync(~0u, s, o);
    if (!lane) g_b2[warp] = s;
}

// ---------------- main fused VQ kernel ----------------
__global__ void __launch_bounds__(256, 1)
vq_kernel(const float* __restrict__ X, const float* __restrict__ C,
          float* __restrict__ quant, float* __restrict__ dist)
{
    extern __shared__ char smem[];
    const uint32_t sb = su32(smem);
    const int t = threadIdx.x;
    const int lane = t & 31;
    const int warp = t >> 5;
    const int wm = warp >> 1;          // 0..3: rows wm*32..+31
    const int wn = warp & 1;           // 0..1: cols wn*64..+63 (within 128-col tile)
    const int rowBase = blockIdx.x * 128;

    float* a2s = (float*)(smem + SM_A2);
    float* b2s = (float*)(smem + SM_B2);

    // ---- load A (128x512) fp32 -> bf16 swizzled smem; fused a2 ----
    {
        int row = t >> 1;
        int kb = (t & 1) * 256;
        const float4* src = (const float4*)(X + (size_t)(rowBase + row) * LATENT + kb);
        float s = 0.f;
#pragma unroll 4
        for (int i = 0; i < 32; i++) {
            float4 a = src[2 * i];
            float4 b = src[2 * i + 1];
            s += a.x * a.x + a.y * a.y + a.z * a.z + a.w * a.w;
            s += b.x * b.x + b.y * b.y + b.z * b.z + b.w * b.w;
            int k = kb + i * 8;
            __nv_bfloat162 q0 = __float22bfloat162_rn(make_float2(a.x, a.y));
            __nv_bfloat162 q1 = __float22bfloat162_rn(make_float2(a.z, a.w));
            __nv_bfloat162 q2 = __float22bfloat162_rn(make_float2(b.x, b.y));
            __nv_bfloat162 q3 = __float22bfloat162_rn(make_float2(b.z, b.w));
            uint4 pk;
            pk.x = *(uint32_t*)&q0; pk.y = *(uint32_t*)&q1;
            pk.z = *(uint32_t*)&q2; pk.w = *(uint32_t*)&q3;
            *(uint4*)(smem + SM_A + swz(toff(row, k))) = pk;
        }
        s += __shfl_xor_sync(~0u, s, 1);
        if (!(t & 1)) a2s[row] = s;
    }
    for (int i = t; i < MCODES; i += 256) b2s[i] = g_b2[i];
    __syncthreads();

    // ldmatrix lane geometry (x4: matrices at lanes 0-7,8-15,16-23,24-31)
    const int mat = lane >> 3;
    const int arow = wm * 32 + (lane & 7) + ((mat & 1) ? 8 : 0);
    const int akd  = (mat & 2) ? 8 : 0;
    const int brow = (lane & 7) + ((mat & 2) ? 8 : 0);
    const int bkd  = (mat & 1) ? 8 : 0;

    const int g = lane >> 2;           // fragment row group
    float my_a2[4];
#pragma unroll
    for (int s = 0; s < 4; s++)
        my_a2[s] = a2s[wm * 32 + (s >> 1) * 16 + (s & 1) * 8 + g];

    float acc[2][8][4];
#pragma unroll
    for (int mt = 0; mt < 2; mt++)
#pragma unroll
        for (int nn = 0; nn < 8; nn++)
#pragma unroll
            for (int e = 0; e < 4; e++) acc[mt][nn][e] = 0.f;

    float bestv[4];
#pragma unroll
    for (int s = 0; s < 4; s++) bestv[s] = 3.4e38f;

    // ---- B chunk loader: global chunk gl = nt*4 + kc (128 codes x 128 k) ----
    auto loadB = [&](int gl) {
        int nt = gl >> 2, kc = gl & 3;
        uint32_t dstb = sb + ((gl & 1) ? SM_B1 : SM_B0);
        const __nv_bfloat16* src = g_cb16 + (size_t)(nt * 128) * LATENT + kc * 128;
#pragma unroll
        for (int j = 0; j < 8; j++) {
            int unit = t + j * 256;
            int row = unit >> 4;
            int k = (unit & 15) * 8;
            cp16(dstb + swz(toff(row, k)), src + (size_t)row * LATENT + k);
        }
        asm volatile("cp.async.commit_group;" ::: "memory");
    };

    loadB(0);
    loadB(1);

    int gl = 0;
#pragma unroll 1
    for (int nt = 0; nt < 8; nt++) {
#pragma unroll 1
        for (int kc = 0; kc < 4; kc++) {
            if (gl < 31) asm volatile("cp.async.wait_group 1;" ::: "memory");
            else         asm volatile("cp.async.wait_group 0;" ::: "memory");
            __syncthreads();

            const uint32_t aB = sb + SM_A;
            const uint32_t bB = sb + ((gl & 1) ? SM_B1 : SM_B0);
#pragma unroll
            for (int ks = 0; ks < 8; ks++) {
                const int ak = kc * 128 + ks * 16 + akd;
                uint32_t a0[4], a1[4];
                ldsm4(aB + swz(toff(arow,      ak)), a0[0], a0[1], a0[2], a0[3]);
                ldsm4(aB + swz(toff(arow + 16, ak)), a1[0], a1[1], a1[2], a1[3]);
                uint32_t bf[8][2];
#pragma unroll
                for (int p = 0; p < 4; p++) {
                    const int br = wn * 64 + p * 16 + brow;
                    const int bk = ks * 16 + bkd;
                    ldsm4(bB + swz(toff(br, bk)),
                          bf[2 * p][0], bf[2 * p][1], bf[2 * p + 1][0], bf[2 * p + 1][1]);
                }
#pragma unroll
                for (int nn = 0; nn < 8; nn++) {
                    mma16816(acc[0][nn], a0[0], a0[1], a0[2], a0[3], bf[nn][0], bf[nn][1]);
                    mma16816(acc[1][nn], a1[0], a1[1], a1[2], a1[3], bf[nn][0], bf[nn][1]);
                }
            }
            __syncthreads();
            if (gl + 2 < 32) loadB(gl + 2);
            gl++;
        }

        // ---- epilogue for this 128-col tile: distances, dist stores, min track ----
        const int colbase = nt * 128 + wn * 64;
#pragma unroll
        for (int mt = 0; mt < 2; mt++) {
            const int rA = wm * 32 + mt * 16 + g;
            const int rB = rA + 8;
            const float a2A = my_a2[mt * 2];
            const float a2B = my_a2[mt * 2 + 1];
            float* dA = dist + (size_t)(rowBase + rA) * MCODES;
            float* dB = dist + (size_t)(rowBase + rB) * MCODES;
#pragma unroll
            for (int nn = 0; nn < 8; nn++) {
                const int c0 = colbase + nn * 8 + (lane & 3) * 2;
                const float b20 = b2s[c0], b21 = b2s[c0 + 1];
                float d0 = fmaf(-2.f, acc[mt][nn][0], a2A + b20);
                float d1 = fmaf(-2.f, acc[mt][nn][1], a2A + b21);
                float d2 = fmaf(-2.f, acc[mt][nn][2], a2B + b20);
                float d3 = fmaf(-2.f, acc[mt][nn][3], a2B + b21);
                bestv[mt * 2]     = fminf(bestv[mt * 2],     fminf(d0, d1));
                bestv[mt * 2 + 1] = fminf(bestv[mt * 2 + 1], fminf(d2, d3));
                *(float2*)(dA + c0) = make_float2(d0, d1);
                *(float2*)(dB + c0) = make_float2(d2, d3);
                acc[mt][nn][0] = 0.f; acc[mt][nn][1] = 0.f;
                acc[mt][nn][2] = 0.f; acc[mt][nn][3] = 0.f;
            }
        }
    }

    // ---- per-row bf16-level min value ----
    float* rv = (float*)(smem + SM_RV);
    float* minvS = (float*)(smem + SM_MINV);
#pragma unroll
    for (int s = 0; s < 4; s++) {
        float v = bestv[s];
        v = fminf(v, __shfl_xor_sync(~0u, v, 1));
        v = fminf(v, __shfl_xor_sync(~0u, v, 2));
        if ((lane & 3) == 0) {
            int row = wm * 32 + (s >> 1) * 16 + (s & 1) * 8 + g;
            rv[row * 2 + wn] = v;
        }
    }
    __syncthreads();
    if (t < 128) minvS[t] = fminf(rv[t * 2], rv[t * 2 + 1]);
    __syncthreads();

    // ================= PHASE 2: exact fp32 rescore of candidates =================
    // warp per row; candidates = codes with bf16-dist <= min + 0.25 (always
    // contains the true fp32 argmin; expected ~1.5 per row).
    int* cnt = (int*)(smem + SM_CNT);
    int* clist = (int*)(smem + SM_CLIST) + warp * 16;

    for (int r = warp; r < 128; r += 8) {
        if (!lane) cnt[warp] = 0;
        __syncwarp();
        const float thr = minvS[r] + 0.25f;
        const float4* drow4 = (const float4*)(dist + (size_t)(rowBase + r) * MCODES);
#pragma unroll
        for (int j = 0; j < 8; j++) {
            float4 v = drow4[lane + 32 * j];
            int base = (lane + 32 * j) * 4;
            if (v.x <= thr) { int p = atomicAdd(&cnt[warp], 1); if (p < 16) clist[p] = base; }
            if (v.y <= thr) { int p = atomicAdd(&cnt[warp], 1); if (p < 16) clist[p] = base + 1; }
            if (v.z <= thr) { int p = atomicAdd(&cnt[warp], 1); if (p < 16) clist[p] = base + 2; }
            if (v.w <= thr) { int p = atomicAdd(&cnt[warp], 1); if (p < 16) clist[p] = base + 3; }
        }
        __syncwarp();
        int m = cnt[warp];
        if (m > 16) m = 16;

        // fp32 x row (16 elems per lane)
        const float4* xr = (const float4*)(X + (size_t)(rowBase + r) * LATENT);
        float4 xv[4];
#pragma unroll
        for (int q = 0; q < 4; q++) xv[q] = xr[lane + 32 * q];
        const float a2r = a2s[r];

        float bs = 3.4e38f;
        int bi = 0x7fffffff;
        for (int ci = 0; ci < m; ci++) {
            int c = clist[ci];
            const float4* cr = (const float4*)(C + (size_t)c * LATENT);
            float s = 0.f;
#pragma unroll
            for (int q = 0; q < 4; q++) {
                float4 cv = cr[lane + 32 * q];
                s += xv[q].x * cv.x + xv[q].y * cv.y + xv[q].z * cv.z + xv[q].w * cv.w;
            }
#pragma unroll
            for (int o = 16; o > 0; o >>= 1) s += __shfl_xor_sync(~0u, s, o);
            // same arithmetic shape as reference: (a2 - 2ab) + b2, fp32 at ~512 scale
            float sc = (a2r - 2.f * s) + b2s[c];
            if (sc < bs || (sc == bs && c < bi)) { bs = sc; bi = c; }
        }

        // write quantized row = C[bi] (fp32), coalesced across the warp
        const float4* src = (const float4*)(C + (size_t)bi * LATENT);
        float4* dst = (float4*)(quant + (size_t)(rowBase + r) * LATENT);
#pragma unroll
        for (int q = 0; q < 4; q++) dst[lane + 32 * q] = src[lane + 32 * q];
    }
}

extern "C" void kernel_launch(void* const* d_in, const int* in_sizes, int n_in,
                              void* d_out, int out_size) {
    const float* X = (const float*)d_in[0];
    const float* C = (const float*)d_in[1];
    const int n = in_sizes[0] / LATENT;              // 65536
    float* quant = (float*)d_out;                    // (n, 512)
    float* dist  = (float*)d_out + (size_t)n * LATENT;

    prep_kernel<<<(MCODES * 32) / 256, 256>>>(C);

    cudaFuncSetAttribute(vq_kernel, cudaFuncAttributeMaxDynamicSharedMemorySize, SM_TOTAL);
    vq_kernel<<<n / 128, 256, SM_TOTAL>>>(X, C, quant, dist);
}

// round 12
// speedup vs baseline: 5.3177x; 1.2206x over previous
#include <cuda_runtime.h>
#include <cuda_bf16.h>
#include <stdint.h>

#define LATENT 512
#define MCODES 1024
#define ROWS_CTA 64

// ---------------- device scratch (no allocs allowed) ----------------
__device__ __nv_bfloat16 g_cb16[MCODES * LATENT];  // bf16 codebook (1MB, L2-resident)
__device__ float g_b2[MCODES];                     // codebook row sumsq (fp32)

// ---------------- smem layout (dynamic) ----------------
#define SM_A2    0                      // 64 floats
#define SM_B2    256                    // 1024 floats -> 4352
#define SM_RV    4352                   // 64*4 floats -> 5376
#define SM_MINV  5376                   // 64 floats -> 5632
#define SM_CNT   5632                   // 8 ints -> 5664
#define SM_CLIST 5664                   // 8*16 ints -> 6176
#define SM_A     8192                   // 64x512 bf16 swizzled (64KB) -> 73728
#define SM_B0    73728                  // 128 codes x 64 k bf16 (16KB)
#define SM_B1    90112
#define SM_TOTAL 106496                 // 104KB -> 2 CTAs/SM

__device__ __forceinline__ uint32_t su32(const void* p) {
    uint32_t a;
    asm("{ .reg .u64 t; cvta.to.shared.u64 t, %1; cvt.u32.u64 %0, t; }" : "=r"(a) : "l"(p));
    return a;
}

// A tile (64 rows x 512 k): 8-row x 64-bf16 atoms; k-group stride 8KB.
__device__ __forceinline__ uint32_t toffA(int row, int k) {
    return (uint32_t)((row >> 3) * 1024 + (k >> 6) * 8192 + (row & 7) * 128 + (k & 63) * 2);
}
// B chunk (128 rows x 64 k): 8-row x 64-bf16 atoms, single k-group.
__device__ __forceinline__ uint32_t toffB(int row, int k) {
    return (uint32_t)((row >> 3) * 1024 + (row & 7) * 128 + (k & 63) * 2);
}
__device__ __forceinline__ uint32_t swz(uint32_t o) { return o ^ ((o >> 3) & 0x70); }

__device__ __forceinline__ void cp16(uint32_t dst, const void* src) {
    asm volatile("cp.async.cg.shared.global [%0], [%1], 16;" :: "r"(dst), "l"(src) : "memory");
}

__device__ __forceinline__ void ldsm4(uint32_t addr, uint32_t& r0, uint32_t& r1,
                                      uint32_t& r2, uint32_t& r3) {
    asm volatile("ldmatrix.sync.aligned.m8n8.x4.shared.b16 {%0,%1,%2,%3}, [%4];"
                 : "=r"(r0), "=r"(r1), "=r"(r2), "=r"(r3) : "r"(addr));
}

__device__ __forceinline__ void mma16816(float* d, uint32_t a0, uint32_t a1, uint32_t a2,
                                         uint32_t a3, uint32_t b0, uint32_t b1) {
    asm volatile(
        "mma.sync.aligned.m16n8k16.row.col.f32.bf16.bf16.f32 "
        "{%0,%1,%2,%3}, {%4,%5,%6,%7}, {%8,%9}, {%0,%1,%2,%3};"
        : "+f"(d[0]), "+f"(d[1]), "+f"(d[2]), "+f"(d[3])
        : "r"(a0), "r"(a1), "r"(a2), "r"(a3), "r"(b0), "r"(b1));
}

// ---------------- prep: bf16 codebook + b2 ----------------
__global__ void prep_kernel(const float* __restrict__ C) {
    int warp = (blockIdx.x * blockDim.x + threadIdx.x) >> 5;
    int lane = threadIdx.x & 31;
    if (warp >= MCODES) return;
    const float4* row = (const float4*)(C + (size_t)warp * LATENT);
    uint2* out = (uint2*)(g_cb16 + (size_t)warp * LATENT);
    float s = 0.f;
#pragma unroll
    for (int i = 0; i < 4; i++) {
        float4 v = row[lane + i * 32];
        s += v.x * v.x + v.y * v.y + v.z * v.z + v.w * v.w;
        __nv_bfloat162 p0 = __float22bfloat162_rn(make_float2(v.x, v.y));
        __nv_bfloat162 p1 = __float22bfloat162_rn(make_float2(v.z, v.w));
        uint2 pk;
        pk.x = *(uint32_t*)&p0;
        pk.y = *(uint32_t*)&p1;
        out[lane + i * 32] = pk;
    }
#pragma unroll
    for (int o = 16; o > 0; o >>= 1) s += __shfl_xor_sync(~0u, s, o);
    if (!lane) g_b2[warp] = s;
}

// ---------------- main fused VQ kernel (64 rows/CTA, 2 CTAs/SM) ----------------
__global__ void __launch_bounds__(256, 2)
vq_kernel(const float* __restrict__ X, const float* __restrict__ C,
          float* __restrict__ quant, float* __restrict__ dist)
{
    extern __shared__ char smem[];
    const uint32_t sb = su32(smem);
    const int t = threadIdx.x;
    const int lane = t & 31;
    const int warp = t >> 5;
    const int wm = warp >> 2;          // 0..1: rows wm*32..+31
    const int wn = warp & 3;           // 0..3: cols wn*32..+31 (within 128-col tile)
    const int rowBase = blockIdx.x * ROWS_CTA;

    float* a2s = (float*)(smem + SM_A2);
    float* b2s = (float*)(smem + SM_B2);

    // ---- load A (64x512) fp32 -> bf16 swizzled smem; fused a2 ----
    {
        int row = t >> 2;              // 0..63
        int kb = (t & 3) * 128;
        const float4* src = (const float4*)(X + (size_t)(rowBase + row) * LATENT + kb);
        float s = 0.f;
#pragma unroll 4
        for (int i = 0; i < 16; i++) {
            float4 a = src[2 * i];
            float4 b = src[2 * i + 1];
            s += a.x * a.x + a.y * a.y + a.z * a.z + a.w * a.w;
            s += b.x * b.x + b.y * b.y + b.z * b.z + b.w * b.w;
            int k = kb + i * 8;
            __nv_bfloat162 q0 = __float22bfloat162_rn(make_float2(a.x, a.y));
            __nv_bfloat162 q1 = __float22bfloat162_rn(make_float2(a.z, a.w));
            __nv_bfloat162 q2 = __float22bfloat162_rn(make_float2(b.x, b.y));
            __nv_bfloat162 q3 = __float22bfloat162_rn(make_float2(b.z, b.w));
            uint4 pk;
            pk.x = *(uint32_t*)&q0; pk.y = *(uint32_t*)&q1;
            pk.z = *(uint32_t*)&q2; pk.w = *(uint32_t*)&q3;
            *(uint4*)(smem + SM_A + swz(toffA(row, k))) = pk;
        }
        s += __shfl_xor_sync(~0u, s, 1);
        s += __shfl_xor_sync(~0u, s, 2);
        if (!(t & 3)) a2s[row] = s;
    }
    for (int i = t; i < MCODES; i += 256) b2s[i] = g_b2[i];
    __syncthreads();

    // ldmatrix lane geometry (x4: matrices at lanes 0-7,8-15,16-23,24-31)
    const int mat = lane >> 3;
    const int arow = wm * 32 + (lane & 7) + ((mat & 1) ? 8 : 0);
    const int akd  = (mat & 2) ? 8 : 0;
    const int brow = (lane & 7) + ((mat & 2) ? 8 : 0);
    const int bkd  = (mat & 1) ? 8 : 0;

    const int g = lane >> 2;           // fragment row group
    float my_a2[4];
#pragma unroll
    for (int s = 0; s < 4; s++)
        my_a2[s] = a2s[wm * 32 + (s >> 1) * 16 + (s & 1) * 8 + g];

    float acc[2][4][4];
#pragma unroll
    for (int mt = 0; mt < 2; mt++)
#pragma unroll
        for (int nn = 0; nn < 4; nn++)
#pragma unroll
            for (int e = 0; e < 4; e++) acc[mt][nn][e] = 0.f;

    float bestv[4];
#pragma unroll
    for (int s = 0; s < 4; s++) bestv[s] = 3.4e38f;

    // ---- B chunk loader: gl = nt*8 + kc; chunk = 128 codes x 64 k (16KB) ----
    auto loadB = [&](int gl) {
        int nt = gl >> 3, kc = gl & 7;
        uint32_t dstb = sb + ((gl & 1) ? SM_B1 : SM_B0);
        const __nv_bfloat16* src = g_cb16 + (size_t)(nt * 128) * LATENT + kc * 64;
#pragma unroll
        for (int j = 0; j < 4; j++) {
            int unit = t + j * 256;        // 0..1023
            int row = unit >> 3;           // 0..127
            int k = (unit & 7) * 8;        // 0..56
            cp16(dstb + swz(toffB(row, k)), src + (size_t)row * LATENT + k);
        }
        asm volatile("cp.async.commit_group;" ::: "memory");
    };

    loadB(0);
    loadB(1);

    int gl = 0;
#pragma unroll 1
    for (int nt = 0; nt < 8; nt++) {
#pragma unroll 1
        for (int kc = 0; kc < 8; kc++) {
            if (gl < 62) asm volatile("cp.async.wait_group 1;" ::: "memory");
            else         asm volatile("cp.async.wait_group 0;" ::: "memory");
            __syncthreads();

            const uint32_t aB = sb + SM_A;
            const uint32_t bB = sb + ((gl & 1) ? SM_B1 : SM_B0);
#pragma unroll
            for (int ks = 0; ks < 4; ks++) {
                const int ak = kc * 64 + ks * 16 + akd;
                uint32_t a0[4], a1[4];
                ldsm4(aB + swz(toffA(arow,      ak)), a0[0], a0[1], a0[2], a0[3]);
                ldsm4(aB + swz(toffA(arow + 16, ak)), a1[0], a1[1], a1[2], a1[3]);
                uint32_t bf[4][2];
#pragma unroll
                for (int p = 0; p < 2; p++) {
                    const int br = wn * 32 + p * 16 + brow;
                    const int bk = ks * 16 + bkd;
                    ldsm4(bB + swz(toffB(br, bk)),
                          bf[2 * p][0], bf[2 * p][1], bf[2 * p + 1][0], bf[2 * p + 1][1]);
                }
#pragma unroll
                for (int nn = 0; nn < 4; nn++) {
                    mma16816(acc[0][nn], a0[0], a0[1], a0[2], a0[3], bf[nn][0], bf[nn][1]);
                    mma16816(acc[1][nn], a1[0], a1[1], a1[2], a1[3], bf[nn][0], bf[nn][1]);
                }
            }
            __syncthreads();
            if (gl + 2 < 64) loadB(gl + 2);
            gl++;
        }

        // ---- epilogue for this 128-col tile: distances, dist stores, min track ----
        const int colbase = nt * 128 + wn * 32;
#pragma unroll
        for (int mt = 0; mt < 2; mt++) {
            const int rA = wm * 32 + mt * 16 + g;
            const int rB = rA + 8;
            const float a2A = my_a2[mt * 2];
            const float a2B = my_a2[mt * 2 + 1];
            float* dA = dist + (size_t)(rowBase + rA) * MCODES;
            float* dB = dist + (size_t)(rowBase + rB) * MCODES;
#pragma unroll
            for (int nn = 0; nn < 4; nn++) {
                const int c0 = colbase + nn * 8 + (lane & 3) * 2;
                const float b20 = b2s[c0], b21 = b2s[c0 + 1];
                float d0 = fmaf(-2.f, acc[mt][nn][0], a2A + b20);
                float d1 = fmaf(-2.f, acc[mt][nn][1], a2A + b21);
                float d2 = fmaf(-2.f, acc[mt][nn][2], a2B + b20);
                float d3 = fmaf(-2.f, acc[mt][nn][3], a2B + b21);
                bestv[mt * 2]     = fminf(bestv[mt * 2],     fminf(d0, d1));
                bestv[mt * 2 + 1] = fminf(bestv[mt * 2 + 1], fminf(d2, d3));
                *(float2*)(dA + c0) = make_float2(d0, d1);
                *(float2*)(dB + c0) = make_float2(d2, d3);
                acc[mt][nn][0] = 0.f; acc[mt][nn][1] = 0.f;
                acc[mt][nn][2] = 0.f; acc[mt][nn][3] = 0.f;
            }
        }
    }

    // ---- per-row bf16-level min value ----
    float* rv = (float*)(smem + SM_RV);
    float* minvS = (float*)(smem + SM_MINV);
#pragma unroll
    for (int s = 0; s < 4; s++) {
        float v = bestv[s];
        v = fminf(v, __shfl_xor_sync(~0u, v, 1));
        v = fminf(v, __shfl_xor_sync(~0u, v, 2));
        if ((lane & 3) == 0) {
            int row = wm * 32 + (s >> 1) * 16 + (s & 1) * 8 + g;
            rv[row * 4 + wn] = v;
        }
    }
    __syncthreads();
    if (t < ROWS_CTA)
        minvS[t] = fminf(fminf(rv[t * 4], rv[t * 4 + 1]),
                         fminf(rv[t * 4 + 2], rv[t * 4 + 3]));
    __syncthreads();

    // ================= PHASE 2: exact fp32 rescore of candidates =================
    int* cnt = (int*)(smem + SM_CNT);
    int* clist = (int*)(smem + SM_CLIST) + warp * 16;

    for (int r = warp; r < ROWS_CTA; r += 8) {
        if (!lane) cnt[warp] = 0;
        __syncwarp();
        const float thr = minvS[r] + 0.25f;
        const float4* drow4 = (const float4*)(dist + (size_t)(rowBase + r) * MCODES);
#pragma unroll
        for (int j = 0; j < 8; j++) {
            float4 v = drow4[lane + 32 * j];
            int base = (lane + 32 * j) * 4;
            if (v.x <= thr) { int p = atomicAdd(&cnt[warp], 1); if (p < 16) clist[p] = base; }
            if (v.y <= thr) { int p = atomicAdd(&cnt[warp], 1); if (p < 16) clist[p] = base + 1; }
            if (v.z <= thr) { int p = atomicAdd(&cnt[warp], 1); if (p < 16) clist[p] = base + 2; }
            if (v.w <= thr) { int p = atomicAdd(&cnt[warp], 1); if (p < 16) clist[p] = base + 3; }
        }
        __syncwarp();
        int m = cnt[warp];
        if (m > 16) m = 16;

        const float4* xr = (const float4*)(X + (size_t)(rowBase + r) * LATENT);
        float4 xv[4];
#pragma unroll
        for (int q = 0; q < 4; q++) xv[q] = xr[lane + 32 * q];
        const float a2r = a2s[r];

        float bs = 3.4e38f;
        int bi = 0x7fffffff;
        for (int ci = 0; ci < m; ci++) {
            int c = clist[ci];
            const float4* cr = (const float4*)(C + (size_t)c * LATENT);
            float s = 0.f;
#pragma unroll
            for (int q = 0; q < 4; q++) {
                float4 cv = cr[lane + 32 * q];
                s += xv[q].x * cv.x + xv[q].y * cv.y + xv[q].z * cv.z + xv[q].w * cv.w;
            }
#pragma unroll
            for (int o = 16; o > 0; o >>= 1) s += __shfl_xor_sync(~0u, s, o);
            float sc = (a2r - 2.f * s) + b2s[c];
            if (sc < bs || (sc == bs && c < bi)) { bs = sc; bi = c; }
        }

        const float4* src = (const float4*)(C + (size_t)bi * LATENT);
        float4* dst = (float4*)(quant + (size_t)(rowBase + r) * LATENT);
#pragma unroll
        for (int q = 0; q < 4; q++) dst[lane + 32 * q] = src[lane + 32 * q];
    }
}

extern "C" void kernel_launch(void* const* d_in, const int* in_sizes, int n_in,
                              void* d_out, int out_size) {
    const float* X = (const float*)d_in[0];
    const float* C = (const float*)d_in[1];
    const int n = in_sizes[0] / LATENT;              // 65536
    float* quant = (float*)d_out;                    // (n, 512)
    float* dist  = (float*)d_out + (size_t)n * LATENT;

    prep_kernel<<<(MCODES * 32) / 256, 256>>>(C);

    cudaFuncSetAttribute(vq_kernel, cudaFuncAttributeMaxDynamicSharedMemorySize, SM_TOTAL);
    vq_kernel<<<n / ROWS_CTA, 256, SM_TOTAL>>>(X, C, quant, dist);
}

// round 16
// speedup vs baseline: 5.3515x; 1.0064x over previous
#include <cuda_runtime.h>
#include <cuda_bf16.h>
#include <stdint.h>

#define LATENT 512
#define MCODES 1024
#define ROWS_CTA 64

// ---------------- device scratch (no allocs allowed) ----------------
__device__ __nv_bfloat16 g_cb16[MCODES * LATENT];  // bf16 codebook (1MB, L2-resident)
__device__ float g_b2[MCODES];                     // codebook row sumsq (fp32)

// ---------------- smem layout (dynamic) ----------------
#define SM_A2    0                      // 64 floats
#define SM_B2    256                    // 1024 floats -> 4352
#define SM_RV    4352                   // 64*4 floats -> 5376
#define SM_MINV  5376                   // 64 floats -> 5632
#define SM_CNT   5632                   // 8 ints -> 5664
#define SM_CLIST 5664                   // 8*16 ints -> 6176
#define SM_A     8192                   // 64x512 bf16 swizzled (64KB) -> 73728
#define SM_B0    73728                  // 128 codes x 64 k bf16 (16KB)
#define SM_B1    90112
#define SM_TOTAL 106496                 // 104KB -> 2 CTAs/SM

__device__ __forceinline__ uint32_t su32(const void* p) {
    uint32_t a;
    asm("{ .reg .u64 t; cvta.to.shared.u64 t, %1; cvt.u32.u64 %0, t; }" : "=r"(a) : "l"(p));
    return a;
}

// A tile (64 rows x 512 k): 8-row x 64-bf16 atoms; k-group stride 8KB.
__device__ __forceinline__ uint32_t toffA(int row, int k) {
    return (uint32_t)((row >> 3) * 1024 + (k >> 6) * 8192 + (row & 7) * 128 + (k & 63) * 2);
}
// B chunk (128 rows x 64 k): 8-row x 64-bf16 atoms, single k-group.
__device__ __forceinline__ uint32_t toffB(int row, int k) {
    return (uint32_t)((row >> 3) * 1024 + (row & 7) * 128 + (k & 63) * 2);
}
__device__ __forceinline__ uint32_t swz(uint32_t o) { return o ^ ((o >> 3) & 0x70); }

__device__ __forceinline__ void cp16(uint32_t dst, const void* src) {
    asm volatile("cp.async.cg.shared.global [%0], [%1], 16;" :: "r"(dst), "l"(src) : "memory");
}

__device__ __forceinline__ void ldsm4(uint32_t addr, uint32_t& r0, uint32_t& r1,
                                      uint32_t& r2, uint32_t& r3) {
    asm volatile("ldmatrix.sync.aligned.m8n8.x4.shared.b16 {%0,%1,%2,%3}, [%4];"
                 : "=r"(r0), "=r"(r1), "=r"(r2), "=r"(r3) : "r"(addr));
}

__device__ __forceinline__ void mma16816(float* d, uint32_t a0, uint32_t a1, uint32_t a2,
                                         uint32_t a3, uint32_t b0, uint32_t b1) {
    asm volatile(
        "mma.sync.aligned.m16n8k16.row.col.f32.bf16.bf16.f32 "
        "{%0,%1,%2,%3}, {%4,%5,%6,%7}, {%8,%9}, {%0,%1,%2,%3};"
        : "+f"(d[0]), "+f"(d[1]), "+f"(d[2]), "+f"(d[3])
        : "r"(a0), "r"(a1), "r"(a2), "r"(a3), "r"(b0), "r"(b1));
}

// ---------------- prep: bf16 codebook + b2 ----------------
__global__ void prep_kernel(const float* __restrict__ C) {
    int warp = (blockIdx.x * blockDim.x + threadIdx.x) >> 5;
    int lane = threadIdx.x & 31;
    if (warp >= MCODES) return;
    const float4* row = (const float4*)(C + (size_t)warp * LATENT);
    uint2* out = (uint2*)(g_cb16 + (size_t)warp * LATENT);
    float s = 0.f;
#pragma unroll
    for (int i = 0; i < 4; i++) {
        float4 v = row[lane + i * 32];
        s += v.x * v.x + v.y * v.y + v.z * v.z + v.w * v.w;
        __nv_bfloat162 p0 = __float22bfloat162_rn(make_float2(v.x, v.y));
        __nv_bfloat162 p1 = __float22bfloat162_rn(make_float2(v.z, v.w));
        uint2 pk;
        pk.x = *(uint32_t*)&p0;
        pk.y = *(uint32_t*)&p1;
        out[lane + i * 32] = pk;
    }
#pragma unroll
    for (int o = 16; o > 0; o >>= 1) s += __shfl_xor_sync(~0u, s, o);
    if (!lane) g_b2[warp] = s;
}

// ---------------- main fused VQ kernel (64 rows/CTA, 2 CTAs/SM) ----------------
__global__ void __launch_bounds__(256, 2)
vq_kernel(const float* __restrict__ X, const float* __restrict__ C,
          float* __restrict__ quant, float* __restrict__ dist)
{
    extern __shared__ char smem[];
    const uint32_t sb = su32(smem);
    const int t = threadIdx.x;
    const int lane = t & 31;
    const int warp = t >> 5;
    const int wm = warp >> 2;          // 0..1: rows wm*32..+31
    const int wn = warp & 3;           // 0..3: cols wn*32..+31 (within 128-col tile)
    const int rowBase = blockIdx.x * ROWS_CTA;

    float* a2s = (float*)(smem + SM_A2);
    float* b2s = (float*)(smem + SM_B2);

    // ---- load A (64x512) fp32 -> bf16 swizzled smem; fused a2 ----
    {
        int row = t >> 2;              // 0..63
        int kb = (t & 3) * 128;
        const float4* src = (const float4*)(X + (size_t)(rowBase + row) * LATENT + kb);
        float s = 0.f;
#pragma unroll 4
        for (int i = 0; i < 16; i++) {
            float4 a = src[2 * i];
            float4 b = src[2 * i + 1];
            s += a.x * a.x + a.y * a.y + a.z * a.z + a.w * a.w;
            s += b.x * b.x + b.y * b.y + b.z * b.z + b.w * b.w;
            int k = kb + i * 8;
            __nv_bfloat162 q0 = __float22bfloat162_rn(make_float2(a.x, a.y));
            __nv_bfloat162 q1 = __float22bfloat162_rn(make_float2(a.z, a.w));
            __nv_bfloat162 q2 = __float22bfloat162_rn(make_float2(b.x, b.y));
            __nv_bfloat162 q3 = __float22bfloat162_rn(make_float2(b.z, b.w));
            uint4 pk;
            pk.x = *(uint32_t*)&q0; pk.y = *(uint32_t*)&q1;
            pk.z = *(uint32_t*)&q2; pk.w = *(uint32_t*)&q3;
            *(uint4*)(smem + SM_A + swz(toffA(row, k))) = pk;
        }
        s += __shfl_xor_sync(~0u, s, 1);
        s += __shfl_xor_sync(~0u, s, 2);
        if (!(t & 3)) a2s[row] = s;
    }
    for (int i = t; i < MCODES; i += 256) b2s[i] = g_b2[i];
    __syncthreads();

    // ldmatrix lane geometry (x4: matrices at lanes 0-7,8-15,16-23,24-31)
    const int mat = lane >> 3;
    const int arow = wm * 32 + (lane & 7) + ((mat & 1) ? 8 : 0);
    const int akd  = (mat & 2) ? 8 : 0;
    const int brow = (lane & 7) + ((mat & 2) ? 8 : 0);
    const int bkd  = (mat & 1) ? 8 : 0;

    // Hoisted swizzled B offsets (8 scalars). B chunk addressing has no kc
    // dependence; buffer base adds (16KB-aligned) never touch swizzle bits 7-9.
    uint32_t bOf0[4], bOf1[4];
#pragma unroll
    for (int ks = 0; ks < 4; ks++) {
        bOf0[ks] = swz(toffB(wn * 32 + brow,      ks * 16 + bkd));
        bOf1[ks] = swz(toffB(wn * 32 + 16 + brow, ks * 16 + bkd));
    }

    const int g = lane >> 2;           // fragment row group
    float my_a2[4];
#pragma unroll
    for (int s = 0; s < 4; s++)
        my_a2[s] = a2s[wm * 32 + (s >> 1) * 16 + (s & 1) * 8 + g];

    float acc[2][4][4];
#pragma unroll
    for (int mt = 0; mt < 2; mt++)
#pragma unroll
        for (int nn = 0; nn < 4; nn++)
#pragma unroll
            for (int e = 0; e < 4; e++) acc[mt][nn][e] = 0.f;

    float bestv[4];
#pragma unroll
    for (int s = 0; s < 4; s++) bestv[s] = 3.4e38f;

    // ---- B chunk loader: gl = nt*8 + kc; chunk = 128 codes x 64 k (16KB) ----
    auto loadB = [&](int gl) {
        int nt = gl >> 3, kc = gl & 7;
        uint32_t dstb = sb + ((gl & 1) ? SM_B1 : SM_B0);
        const __nv_bfloat16* src = g_cb16 + (size_t)(nt * 128) * LATENT + kc * 64;
#pragma unroll
        for (int j = 0; j < 4; j++) {
            int unit = t + j * 256;        // 0..1023
            int row = unit >> 3;           // 0..127
            int k = (unit & 7) * 8;        // 0..56
            cp16(dstb + swz(toffB(row, k)), src + (size_t)row * LATENT + k);
        }
        asm volatile("cp.async.commit_group;" ::: "memory");
    };

    loadB(0);
    loadB(1);

    int gl = 0;
#pragma unroll 1
    for (int nt = 0; nt < 8; nt++) {
#pragma unroll 1
        for (int kc = 0; kc < 8; kc++) {
            if (gl < 62) asm volatile("cp.async.wait_group 1;" ::: "memory");
            else         asm volatile("cp.async.wait_group 0;" ::: "memory");
            __syncthreads();

            const uint32_t aB = sb + SM_A;
            const uint32_t bB = sb + ((gl & 1) ? SM_B1 : SM_B0);
#pragma unroll
            for (int ks = 0; ks < 4; ks++) {
                const int ak = kc * 64 + ks * 16 + akd;
                uint32_t a0[4], a1[4];
                ldsm4(aB + swz(toffA(arow,      ak)), a0[0], a0[1], a0[2], a0[3]);
                ldsm4(aB + swz(toffA(arow + 16, ak)), a1[0], a1[1], a1[2], a1[3]);
                uint32_t bf[4][2];
                ldsm4(bB + bOf0[ks], bf[0][0], bf[0][1], bf[1][0], bf[1][1]);
                ldsm4(bB + bOf1[ks], bf[2][0], bf[2][1], bf[3][0], bf[3][1]);
#pragma unroll
                for (int nn = 0; nn < 4; nn++) {
                    mma16816(acc[0][nn], a0[0], a0[1], a0[2], a0[3], bf[nn][0], bf[nn][1]);
                    mma16816(acc[1][nn], a1[0], a1[1], a1[2], a1[3], bf[nn][0], bf[nn][1]);
                }
            }
            __syncthreads();
            if (gl + 2 < 64) loadB(gl + 2);
            gl++;
        }

        // ---- epilogue for this 128-col tile: distances, dist stores, min track ----
        const int colbase = nt * 128 + wn * 32;
#pragma unroll
        for (int mt = 0; mt < 2; mt++) {
            const int rA = wm * 32 + mt * 16 + g;
            const int rB = rA + 8;
            const float a2A = my_a2[mt * 2];
            const float a2B = my_a2[mt * 2 + 1];
            float* dA = dist + (size_t)(rowBase + rA) * MCODES;
            float* dB = dist + (size_t)(rowBase + rB) * MCODES;
#pragma unroll
            for (int nn = 0; nn < 4; nn++) {
                const int c0 = colbase + nn * 8 + (lane & 3) * 2;
                const float2 b2p = *(const float2*)&b2s[c0];
                float d0 = fmaf(-2.f, acc[mt][nn][0], a2A + b2p.x);
                float d1 = fmaf(-2.f, acc[mt][nn][1], a2A + b2p.y);
                float d2 = fmaf(-2.f, acc[mt][nn][2], a2B + b2p.x);
                float d3 = fmaf(-2.f, acc[mt][nn][3], a2B + b2p.y);
                bestv[mt * 2]     = fminf(bestv[mt * 2],     fminf(d0, d1));
                bestv[mt * 2 + 1] = fminf(bestv[mt * 2 + 1], fminf(d2, d3));
                *(float2*)(dA + c0) = make_float2(d0, d1);
                *(float2*)(dB + c0) = make_float2(d2, d3);
                acc[mt][nn][0] = 0.f; acc[mt][nn][1] = 0.f;
                acc[mt][nn][2] = 0.f; acc[mt][nn][3] = 0.f;
            }
        }
    }

    // ---- per-row bf16-level min value ----
    float* rv = (float*)(smem + SM_RV);
    float* minvS = (float*)(smem + SM_MINV);
#pragma unroll
    for (int s = 0; s < 4; s++) {
        float v = bestv[s];
        v = fminf(v, __shfl_xor_sync(~0u, v, 1));
        v = fminf(v, __shfl_xor_sync(~0u, v, 2));
        if ((lane & 3) == 0) {
            int row = wm * 32 + (s >> 1) * 16 + (s & 1) * 8 + g;
            rv[row * 4 + wn] = v;
        }
    }
    __syncthreads();
    if (t < ROWS_CTA)
        minvS[t] = fminf(fminf(rv[t * 4], rv[t * 4 + 1]),
                         fminf(rv[t * 4 + 2], rv[t * 4 + 3]));
    __syncthreads();

    // ================= PHASE 2: exact fp32 rescore of candidates =================
    int* cnt = (int*)(smem + SM_CNT);
    int* clist = (int*)(smem + SM_CLIST) + warp * 16;

    for (int r = warp; r < ROWS_CTA; r += 8) {
        if (!lane) cnt[warp] = 0;
        __syncwarp();
        const float thr = minvS[r] + 0.25f;
        const float4* drow4 = (const float4*)(dist + (size_t)(rowBase + r) * MCODES);
#pragma unroll
        for (int j = 0; j < 8; j++) {
            float4 v = drow4[lane + 32 * j];
            int base = (lane + 32 * j) * 4;
            if (v.x <= thr) { int p = atomicAdd(&cnt[warp], 1); if (p < 16) clist[p] = base; }
            if (v.y <= thr) { int p = atomicAdd(&cnt[warp], 1); if (p < 16) clist[p] = base + 1; }
            if (v.z <= thr) { int p = atomicAdd(&cnt[warp], 1); if (p < 16) clist[p] = base + 2; }
            if (v.w <= thr) { int p = atomicAdd(&cnt[warp], 1); if (p < 16) clist[p] = base + 3; }
        }
        __syncwarp();
        int m = cnt[warp];
        if (m > 16) m = 16;

        const float4* xr = (const float4*)(X + (size_t)(rowBase + r) * LATENT);
        float4 xv[4];
#pragma unroll
        for (int q = 0; q < 4; q++) xv[q] = xr[lane + 32 * q];
        const float a2r = a2s[r];

        float bs = 3.4e38f;
        int bi = 0x7fffffff;
        for (int ci = 0; ci < m; ci++) {
            int c = clist[ci];
            const float4* cr = (const float4*)(C + (size_t)c * LATENT);
            float s = 0.f;
#pragma unroll
            for (int q = 0; q < 4; q++) {
                float4 cv = cr[lane + 32 * q];
                s += xv[q].x * cv.x + xv[q].y * cv.y + xv[q].z * cv.z + xv[q].w * cv.w;
            }
#pragma unroll
            for (int o = 16; o > 0; o >>= 1) s += __shfl_xor_sync(~0u, s, o);
            float sc = (a2r - 2.f * s) + b2s[c];
            if (sc < bs || (sc == bs && c < bi)) { bs = sc; bi = c; }
        }

        const float4* src = (const float4*)(C + (size_t)bi * LATENT);
        float4* dst = (float4*)(quant + (size_t)(rowBase + r) * LATENT);
#pragma unroll
        for (int q = 0; q < 4; q++) dst[lane + 32 * q] = src[lane + 32 * q];
    }
}

extern "C" void kernel_launch(void* const* d_in, const int* in_sizes, int n_in,
                              void* d_out, int out_size) {
    const float* X = (const float*)d_in[0];
    const float* C = (const float*)d_in[1];
    const int n = in_sizes[0] / LATENT;              // 65536
    float* quant = (float*)d_out;                    // (n, 512)
    float* dist  = (float*)d_out + (size_t)n * LATENT;

    prep_kernel<<<(MCODES * 32) / 256, 256>>>(C);

    cudaFuncSetAttribute(vq_kernel, cudaFuncAttributeMaxDynamicSharedMemorySize, SM_TOTAL);
    vq_kernel<<<n / ROWS_CTA, 256, SM_TOTAL>>>(X, C, quant, dist);
}